// round 12
// baseline (speedup 1.0000x reference)
#include <cuda_runtime.h>
#include <cuda_bf16.h>
#include <cstdint>

#define ALPHA 0.01f

// ---------------------------------------------------------------------------
// Scratch (static device globals — allocation-free per harness rules)
// ---------------------------------------------------------------------------
__device__ float g_h1[32u*64u*112u*112u];        // 102.8 MB conv1 pooled out (fp32)
__device__ float g_h2[32u*64u*56u*56u];          //  25.7 MB conv2 pooled out
__device__ float g_fcp[196*32*10];               // FC split-K partials
__device__ unsigned long long g_w2t_hi[9*1024];  // w2 [tap][oc][ic] bf16 hi (16 ULL/oc)
__device__ unsigned long long g_w2t_lo[9*1024];  // ... bf16 lo
__device__ unsigned long long g_w1t_hi[640];     // w1 [oc][k0..39] bf16 hi (pad-80B rows)
__device__ unsigned long long g_w1t_lo[640];     // ... bf16 lo

__device__ __forceinline__ uint32_t smem_to_u32(const void* p) {
    uint32_t a;
    asm("{ .reg .u64 t; cvta.to.shared.u64 t, %1; cvt.u32.u64 %0, t; }" : "=r"(a) : "l"(p));
    return a;
}
__device__ __forceinline__ void ldsm_x4(uint32_t* r, uint32_t addr) {
    asm volatile("ldmatrix.sync.aligned.m8n8.x4.shared.b16 {%0,%1,%2,%3}, [%4];"
                 : "=r"(r[0]), "=r"(r[1]), "=r"(r[2]), "=r"(r[3]) : "r"(addr));
}
__device__ __forceinline__ void mma_bf16(float* d, const uint32_t* a,
                                         uint32_t b0, uint32_t b1) {
    asm volatile("mma.sync.aligned.m16n8k16.row.col.f32.bf16.bf16.f32 "
                 "{%0,%1,%2,%3}, {%4,%5,%6,%7}, {%8,%9}, {%0,%1,%2,%3};"
                 : "+f"(d[0]), "+f"(d[1]), "+f"(d[2]), "+f"(d[3])
                 : "r"(a[0]), "r"(a[1]), "r"(a[2]), "r"(a[3]), "r"(b0), "r"(b1));
}
__device__ __forceinline__ float leaky(float v) { return v > 0.f ? v : ALPHA * v; }

// ---------------------------------------------------------------------------
// Kernel 0a: w2 -> g_w2t_{hi,lo}[tap][oc][ic] bf16 (proven)
// ---------------------------------------------------------------------------
__global__ void prep_w2_kernel(const float* __restrict__ w2)
{
    int i = blockIdx.x * blockDim.x + threadIdx.x;
    if (i >= 9*64*64) return;
    int tap = i / 4096, r = i % 4096;
    int oc = r / 64, ic = r % 64;
    float v = w2[(oc*64 + ic)*9 + tap];
    __nv_bfloat16 hi = __float2bfloat16(v);
    __nv_bfloat16 lo = __float2bfloat16(v - __bfloat162float(hi));
    ((__nv_bfloat16*)g_w2t_hi)[i] = hi;
    ((__nv_bfloat16*)g_w2t_lo)[i] = lo;
}

// ---------------------------------------------------------------------------
// Kernel 0b: w1 -> g_w1t_{hi,lo}[oc][k] bf16, k = c*9+ky*3+kx (27 real, pad to 40)
// ---------------------------------------------------------------------------
__global__ void prep_w1_kernel(const float* __restrict__ w1)
{
    int i = blockIdx.x * blockDim.x + threadIdx.x;
    if (i >= 64*40) return;
    int oc = i / 40, k = i % 40;
    float v = (k < 27) ? w1[oc*27 + k] : 0.f;
    __nv_bfloat16 hi = __float2bfloat16(v);
    __nv_bfloat16 lo = __float2bfloat16(v - __bfloat162float(hi));
    ((__nv_bfloat16*)g_w1t_hi)[i] = hi;
    ((__nv_bfloat16*)g_w1t_lo)[i] = lo;
}

// ---------------------------------------------------------------------------
// Kernel 1: conv1(3->64) + leaky + maxpool2 via mma.sync (im2col, K=27->32).
// Block 256 thr / 8 warps, tile 16y x 8x = 128 conv pixels x 64 oc.
// A[pixel][k] bf16 hi/lo rows padded to 80B (conflict-free ldmatrix);
// B[oc][k] same. 2 k-steps x 3 passes = 48 mma/warp.
// Epilogue identical in structure to conv2 (proven).
// ---------------------------------------------------------------------------
#define C1_X     256
#define C1_AHI   2560
#define C1_ALO   12800
#define C1_BHI   23040
#define C1_BLO   28160
#define C1_TOTAL 35328        // D overlay [2560, 35328) = 32 KB

__global__ __launch_bounds__(256) void conv1_kernel(const float* __restrict__ x,
                                                    const float* __restrict__ b1)
{
    __shared__ __align__(16) char smem[C1_TOTAL];
    const uint32_t sb = smem_to_u32(smem);
    const int tid  = threadIdx.x;
    const int lane = tid & 31;
    const int wid  = tid >> 5;

    const int t = blockIdx.x;               // 0..391 = 14 (y,16) x 28 (x,8)
    const int b = blockIdx.y;
    const int cy0 = (t / 28) * 16;
    const int cx0 = (t % 28) * 8;

    float* s_bias = (float*)smem;
    float* s_x    = (float*)(smem + C1_X);  // [3][18][10]
    if (tid < 64) s_bias[tid] = b1[tid];

    // phase 1: raw x tile + weight copy (already padded layout in global)
    for (int i = tid; i < 540; i += 256) {
        int c = i / 180, pos = i % 180;
        int r = pos / 10, col = pos % 10;
        int gy = cy0 - 1 + r, gx = cx0 - 1 + col;
        float v = 0.f;
        if (gy >= 0 && gy < 224 && gx >= 0 && gx < 224)
            v = x[((b*3 + c)*224 + gy)*224 + gx];
        s_x[i] = v;
    }
    for (int i = tid; i < 640; i += 256) {
        ((unsigned long long*)(smem + C1_BHI))[i] = g_w1t_hi[i];
        ((unsigned long long*)(smem + C1_BLO))[i] = g_w1t_lo[i];
    }
    __syncthreads();

    // phase 2: im2col A[p][k] hi/lo (zero pad k=27..31)
    {
        __nv_bfloat16* a_hi = (__nv_bfloat16*)(smem + C1_AHI);
        __nv_bfloat16* a_lo = (__nv_bfloat16*)(smem + C1_ALO);
        for (int i = tid; i < 128*32; i += 256) {
            int p = i >> 5, k = i & 31;
            float v = 0.f;
            if (k < 27) {
                int c = k / 9, rem = k % 9;
                int ky = rem / 3, kx = rem % 3;
                int py = p >> 3, px = p & 7;
                v = s_x[c*180 + (py + ky)*10 + (px + kx)];
            }
            __nv_bfloat16 hi = __float2bfloat16(v);
            __nv_bfloat16 lo = __float2bfloat16(v - __bfloat162float(hi));
            a_hi[p*40 + k] = hi;
            a_lo[p*40 + k] = lo;
        }
    }
    __syncthreads();

    // phase 3: mainloop — warp w: pixels [16w,16w+16), all 64 oc
    uint32_t aBase = sb + C1_AHI + (uint32_t)(wid*16 + (lane & 15))*80u
                   + (uint32_t)(lane >> 4)*16u;
    uint32_t bBase[4];
    #pragma unroll
    for (int nb = 0; nb < 4; nb++) {
        int ocrow = nb*16 + (lane & 7) + ((lane >> 4) & 1)*8;
        bBase[nb] = sb + C1_BHI + (uint32_t)ocrow*80u + (uint32_t)((lane >> 3) & 1)*16u;
    }

    float acc[8][4];
    #pragma unroll
    for (int nf = 0; nf < 8; nf++)
        #pragma unroll
        for (int c = 0; c < 4; c++) acc[nf][c] = 0.f;

    #pragma unroll
    for (int k = 0; k < 2; k++) {
        const uint32_t ko = (uint32_t)k * 32u;
        uint32_t ah[4], al[4];
        ldsm_x4(ah, aBase + ko);
        ldsm_x4(al, aBase + 10240u + ko);
        #pragma unroll
        for (int nb = 0; nb < 4; nb++) {
            uint32_t bh[4], bl[4];
            const uint32_t bbadr = bBase[nb] + ko;
            ldsm_x4(bh, bbadr);
            ldsm_x4(bl, bbadr + 5120u);
            mma_bf16(acc[2*nb],   ah, bh[0], bh[1]);
            mma_bf16(acc[2*nb+1], ah, bh[2], bh[3]);
            mma_bf16(acc[2*nb],   ah, bl[0], bl[1]);
            mma_bf16(acc[2*nb+1], ah, bl[2], bl[3]);
            mma_bf16(acc[2*nb],   al, bh[0], bh[1]);
            mma_bf16(acc[2*nb+1], al, bh[2], bh[3]);
        }
    }
    __syncthreads();

    // phase 4: D stage (proven layout) + scalar pool + store to g_h1
    float* s_d = (float*)(smem + C1_AHI);
    #pragma unroll
    for (int nf = 0; nf < 8; nf++) {
        int oc = nf*8 + 2*(lane & 3);
        int p0 = wid*16 + (lane >> 2);
        s_d[p0*64 + oc]         = acc[nf][0];
        s_d[p0*64 + oc + 1]     = acc[nf][1];
        s_d[(p0+8)*64 + oc]     = acc[nf][2];
        s_d[(p0+8)*64 + oc + 1] = acc[nf][3];
    }
    __syncthreads();

    {
        int q   = tid >> 3;
        int oc0 = (tid & 7) * 8;
        int qy = q >> 2, qx = q & 3;
        int p00 = (qy*2)*8 + qx*2;
        int oy = (cy0 >> 1) + qy, ox = (cx0 >> 1) + qx;
        #pragma unroll
        for (int j = 0; j < 8; j++) {
            int oc = oc0 + j;
            float m = fmaxf(fmaxf(s_d[p00*64 + oc],     s_d[(p00+1)*64 + oc]),
                            fmaxf(s_d[(p00+8)*64 + oc], s_d[(p00+9)*64 + oc]));
            g_h1[(((unsigned)(b*64 + oc))*112u + oy)*112u + ox] = leaky(m + s_bias[oc]);
        }
    }
}

// ---------------------------------------------------------------------------
// Kernel 2: conv2(64->64) + leaky + maxpool2 via mma.sync (proven R11; zeroing
// pass removed — every ldsm-read byte is written by staging).
// ---------------------------------------------------------------------------
#define C2_AHI   256
#define C2_ALO   26176
#define C2_WHI   52096
#define C2_WLO   135040
#define C2_TOTAL 217984
#define C2_ALO_D 25920
#define C2_WLO_D 82944

__global__ __launch_bounds__(256) void conv2_kernel(const float* __restrict__ b2)
{
    extern __shared__ __align__(16) char smem[];
    const uint32_t sb = smem_to_u32(smem);
    const int tid  = threadIdx.x;
    const int lane = tid & 31;
    const int wid  = tid >> 5;

    const int t = blockIdx.x;               // 0..97 = 7 (y,16) x 14 (x,8)
    const int b = blockIdx.y;
    const int cy0 = (t / 14) * 16;
    const int cx0 = (t % 14) * 8;

    float* s_bias = (float*)smem;
    if (tid < 64) s_bias[tid] = b2[tid];

    for (int i = tid; i < 9*1024; i += 256) {
        int tap = i >> 10, r = i & 1023;
        int oc = r >> 4, icg = r & 15;
        uint32_t doff = (uint32_t)tap*9216u + (uint32_t)oc*144u + (uint32_t)icg*8u;
        *(unsigned long long*)(smem + C2_WHI + doff) = g_w2t_hi[i];
        *(unsigned long long*)(smem + C2_WLO + doff) = g_w2t_lo[i];
    }

    {
        __nv_bfloat16* s_ahi = (__nv_bfloat16*)(smem + C2_AHI);
        __nv_bfloat16* s_alo = (__nv_bfloat16*)(smem + C2_ALO);
        for (int i = tid; i < 64*180; i += 256) {
            int ic  = i / 180;
            int pos = i % 180;
            int r = pos / 10, c = pos % 10;
            int gy = cy0 - 1 + r, gx = cx0 - 1 + c;
            float v = 0.f;
            if (gy >= 0 && gy < 112 && gx >= 0 && gx < 112)
                v = g_h1[(((unsigned)(b*64 + ic))*112u + gy)*112u + gx];
            __nv_bfloat16 hi = __float2bfloat16(v);
            __nv_bfloat16 lo = __float2bfloat16(v - __bfloat162float(hi));
            s_ahi[pos*72 + ic] = hi;
            s_alo[pos*72 + ic] = lo;
        }
    }
    __syncthreads();

    uint32_t aBase;
    {
        int p = wid*16 + (lane & 15);
        int pos = (p >> 3)*10 + (p & 7);
        aBase = sb + C2_AHI + (uint32_t)pos*144u + (uint32_t)(lane >> 4)*16u;
    }
    uint32_t bBase[4];
    #pragma unroll
    for (int nb = 0; nb < 4; nb++) {
        int ocrow = nb*16 + (lane & 7) + ((lane >> 4) & 1)*8;
        bBase[nb] = sb + C2_WHI + (uint32_t)ocrow*144u + (uint32_t)((lane >> 3) & 1)*16u;
    }

    float acc[8][4];
    #pragma unroll
    for (int nf = 0; nf < 8; nf++)
        #pragma unroll
        for (int c = 0; c < 4; c++) acc[nf][c] = 0.f;

    #pragma unroll
    for (int tap = 0; tap < 9; tap++) {
        const uint32_t aS = (uint32_t)((tap/3)*10 + (tap%3)) * 144u;
        const uint32_t wS = (uint32_t)tap * 9216u;
        #pragma unroll
        for (int k = 0; k < 4; k++) {
            const uint32_t ko = (uint32_t)k * 32u;
            uint32_t ah[4], al[4];
            ldsm_x4(ah, aBase + aS + ko);
            ldsm_x4(al, aBase + C2_ALO_D + aS + ko);
            #pragma unroll
            for (int nb = 0; nb < 4; nb++) {
                uint32_t bh[4], bl[4];
                const uint32_t bbadr = bBase[nb] + wS + ko;
                ldsm_x4(bh, bbadr);
                ldsm_x4(bl, bbadr + C2_WLO_D);
                mma_bf16(acc[2*nb],   ah, bh[0], bh[1]);
                mma_bf16(acc[2*nb+1], ah, bh[2], bh[3]);
                mma_bf16(acc[2*nb],   ah, bl[0], bl[1]);
                mma_bf16(acc[2*nb+1], ah, bl[2], bl[3]);
                mma_bf16(acc[2*nb],   al, bh[0], bh[1]);
                mma_bf16(acc[2*nb+1], al, bh[2], bh[3]);
            }
        }
    }
    __syncthreads();

    float* s_d = (float*)(smem + C2_AHI);
    #pragma unroll
    for (int nf = 0; nf < 8; nf++) {
        int oc = nf*8 + 2*(lane & 3);
        int p0 = wid*16 + (lane >> 2);
        s_d[p0*64 + oc]         = acc[nf][0];
        s_d[p0*64 + oc + 1]     = acc[nf][1];
        s_d[(p0+8)*64 + oc]     = acc[nf][2];
        s_d[(p0+8)*64 + oc + 1] = acc[nf][3];
    }
    __syncthreads();

    {
        int q   = tid >> 3;
        int oc0 = (tid & 7) * 8;
        int qy = q >> 2, qx = q & 3;
        int p00 = (qy*2)*8 + qx*2;
        int oy = (cy0 >> 1) + qy, ox = (cx0 >> 1) + qx;
        #pragma unroll
        for (int j = 0; j < 8; j++) {
            int oc = oc0 + j;
            float m = fmaxf(fmaxf(s_d[p00*64 + oc],     s_d[(p00+1)*64 + oc]),
                            fmaxf(s_d[(p00+8)*64 + oc], s_d[(p00+9)*64 + oc]));
            g_h2[(((unsigned)(b*64 + oc))*56u + oy)*56u + ox] = leaky(m + s_bias[oc]);
        }
    }
}

// ---------------------------------------------------------------------------
// Kernel 3: FC split-K partials. Grid (196,4): block = 1 k-chunk x 8 batches,
// warp = batch (serial bg loop removed for occupancy).
// ---------------------------------------------------------------------------
__global__ __launch_bounds__(256) void fc_partial_kernel(const float* __restrict__ wfc)
{
    __shared__ __align__(16) float s_wt[10][1024];
    const int tid = threadIdx.x;
    const int k0  = blockIdx.x * 1024;

    for (int i = tid; i < 10240; i += 256) {
        int k = i / 10, c = i % 10;
        s_wt[c][k] = wfc[k0*10 + i];
    }
    __syncthreads();

    const int warp = tid >> 5, lane = tid & 31;
    const int b = blockIdx.y * 8 + warp;

    float acc[10];
    #pragma unroll
    for (int c = 0; c < 10; c++) acc[c] = 0.f;

    const float4* hb = (const float4*)&g_h2[b*200704 + k0];
    for (int k4 = lane; k4 < 256; k4 += 32) {
        float4 hv = hb[k4];
        #pragma unroll
        for (int c = 0; c < 10; c++) {
            float4 wv = *(const float4*)&s_wt[c][k4*4];
            acc[c] += hv.x*wv.x + hv.y*wv.y + hv.z*wv.z + hv.w*wv.w;
        }
    }
    #pragma unroll
    for (int c = 0; c < 10; c++) {
        #pragma unroll
        for (int off = 16; off; off >>= 1)
            acc[c] += __shfl_xor_sync(0xffffffffu, acc[c], off);
    }
    if (lane == 0) {
        #pragma unroll
        for (int c = 0; c < 10; c++)
            g_fcp[(blockIdx.x*32 + b)*10 + c] = acc[c];
    }
}

// ---------------------------------------------------------------------------
// Kernel 4: final deterministic reduction (proven)
// ---------------------------------------------------------------------------
__global__ __launch_bounds__(224) void fc_reduce_kernel(const float* __restrict__ bfc,
                                                        float* __restrict__ out)
{
    __shared__ float s_part[7][10];
    const int tid = threadIdx.x;
    const int b   = blockIdx.x;
    const int warp = tid >> 5, lane = tid & 31;

    float a[10];
    #pragma unroll
    for (int c = 0; c < 10; c++) a[c] = 0.f;

    if (tid < 196) {
        const float2* p = (const float2*)&g_fcp[(tid*32 + b)*10];
        #pragma unroll
        for (int h = 0; h < 5; h++) {
            float2 v = p[h];
            a[2*h]   = v.x;
            a[2*h+1] = v.y;
        }
    }
    #pragma unroll
    for (int c = 0; c < 10; c++) {
        #pragma unroll
        for (int off = 16; off; off >>= 1)
            a[c] += __shfl_xor_sync(0xffffffffu, a[c], off);
    }
    if (lane == 0)
        #pragma unroll
        for (int c = 0; c < 10; c++) s_part[warp][c] = a[c];
    __syncthreads();

    if (tid < 10) {
        float s = bfc[tid];
        #pragma unroll
        for (int w = 0; w < 7; w++) s += s_part[w][tid];
        out[b*10 + tid] = s;
    }
}

// ---------------------------------------------------------------------------
extern "C" void kernel_launch(void* const* d_in, const int* in_sizes, int n_in,
                              void* d_out, int out_size)
{
    const float* x   = (const float*)d_in[0];
    const float* w1  = (const float*)d_in[1];
    const float* b1  = (const float*)d_in[2];
    const float* w2  = (const float*)d_in[3];
    const float* b2  = (const float*)d_in[4];
    const float* wfc = (const float*)d_in[5];
    const float* bfc = (const float*)d_in[6];
    float* out = (float*)d_out;

    cudaFuncSetAttribute(conv2_kernel, cudaFuncAttributeMaxDynamicSharedMemorySize,
                         C2_TOTAL);

    prep_w1_kernel<<<3, 1024>>>(w1);
    prep_w2_kernel<<<36, 1024>>>(w2);
    conv1_kernel<<<dim3(392, 32), 256>>>(x, b1);
    conv2_kernel<<<dim3(98, 32), 256, C2_TOTAL>>>(b2);
    fc_partial_kernel<<<dim3(196, 4), 256>>>(wfc);
    fc_reduce_kernel<<<32, 224>>>(bfc, out);
}

// round 14
// speedup vs baseline: 1.4963x; 1.4963x over previous
#include <cuda_runtime.h>
#include <cuda_bf16.h>
#include <cstdint>

#define ALPHA 0.01f

// ---------------------------------------------------------------------------
// Scratch (static device globals — allocation-free per harness rules)
// ---------------------------------------------------------------------------
__device__ float g_h1[32u*64u*112u*112u];        // 102.8 MB conv1 pooled out (fp32)
__device__ float g_h2[32u*64u*56u*56u];          //  25.7 MB conv2 pooled out
__device__ float g_fcp[196*32*10];               // FC split-K partials
__device__ unsigned long long g_w2t_hi[9*1024];  // w2 [tap][oc][ic] bf16 hi (16 ULL/oc)
__device__ unsigned long long g_w2t_lo[9*1024];  // ... bf16 lo

__device__ __forceinline__ uint32_t smem_to_u32(const void* p) {
    uint32_t a;
    asm("{ .reg .u64 t; cvta.to.shared.u64 t, %1; cvt.u32.u64 %0, t; }" : "=r"(a) : "l"(p));
    return a;
}
__device__ __forceinline__ void ldsm_x4(uint32_t* r, uint32_t addr) {
    asm volatile("ldmatrix.sync.aligned.m8n8.x4.shared.b16 {%0,%1,%2,%3}, [%4];"
                 : "=r"(r[0]), "=r"(r[1]), "=r"(r[2]), "=r"(r[3]) : "r"(addr));
}
__device__ __forceinline__ void mma_bf16(float* d, const uint32_t* a,
                                         uint32_t b0, uint32_t b1) {
    asm volatile("mma.sync.aligned.m16n8k16.row.col.f32.bf16.bf16.f32 "
                 "{%0,%1,%2,%3}, {%4,%5,%6,%7}, {%8,%9}, {%0,%1,%2,%3};"
                 : "+f"(d[0]), "+f"(d[1]), "+f"(d[2]), "+f"(d[3])
                 : "r"(a[0]), "r"(a[1]), "r"(a[2]), "r"(a[3]), "r"(b0), "r"(b1));
}
__device__ __forceinline__ void cp_async16(uint32_t dst, const void* src) {
    asm volatile("cp.async.cg.shared.global [%0], [%1], 16;" :: "r"(dst), "l"(src));
}
#define CP_COMMIT() asm volatile("cp.async.commit_group;" ::: "memory")
#define CP_WAIT0()  asm volatile("cp.async.wait_group 0;" ::: "memory")

// ---- packed f32x2 helpers (conv1, proven) ----
__device__ __forceinline__ unsigned long long pack2(float x, float y) {
    unsigned long long r;
    asm("mov.b64 %0, {%1, %2};" : "=l"(r) : "f"(x), "f"(y));
    return r;
}
__device__ __forceinline__ unsigned long long ffma2(unsigned long long a,
                                                    unsigned long long b,
                                                    unsigned long long c) {
    unsigned long long d;
    asm("fma.rn.f32x2 %0, %1, %2, %3;" : "=l"(d) : "l"(a), "l"(b), "l"(c));
    return d;
}
__device__ __forceinline__ void unpack2(unsigned long long v, float& x, float& y) {
    asm("mov.b64 {%0, %1}, %2;" : "=f"(x), "=f"(y) : "l"(v));
}
__device__ __forceinline__ float leaky(float v) { return v > 0.f ? v : ALPHA * v; }

// ---------------------------------------------------------------------------
// Kernel 0: w2 -> g_w2t_{hi,lo}[tap][oc][ic] bf16 (proven)
// ---------------------------------------------------------------------------
__global__ void prep_w2_kernel(const float* __restrict__ w2)
{
    int i = blockIdx.x * blockDim.x + threadIdx.x;
    if (i >= 9*64*64) return;
    int tap = i / 4096, r = i % 4096;
    int oc = r / 64, ic = r % 64;
    float v = w2[(oc*64 + ic)*9 + tap];
    __nv_bfloat16 hi = __float2bfloat16(v);
    __nv_bfloat16 lo = __float2bfloat16(v - __bfloat162float(hi));
    ((__nv_bfloat16*)g_w2t_hi)[i] = hi;
    ((__nv_bfloat16*)g_w2t_lo)[i] = lo;
}

// ---------------------------------------------------------------------------
// Kernel 1: conv1(3->64) + leaky + maxpool2, f32x2-packed (R11 proven)
// ---------------------------------------------------------------------------
__global__ __launch_bounds__(256) void conv1_kernel(const float* __restrict__ x,
                                                    const float* __restrict__ w1,
                                                    const float* __restrict__ b1)
{
    __shared__ float s_in[3][34][34];
    __shared__ __align__(16) float s_w2[27][64];
    __shared__ float s_b[64];

    const int tid  = threadIdx.x;
    const int t    = blockIdx.x;          // 0..48
    const int b    = blockIdx.y;
    const int tpy0 = (t / 7) * 16;
    const int tpx0 = (t % 7) * 16;
    const int cy0  = tpy0 * 2, cx0 = tpx0 * 2;

    for (int i = tid; i < 3*34*34; i += 256) {
        int c  = i / (34*34); int r = i % (34*34);
        int yy = r / 34, xx = r % 34;
        int gy = cy0 - 1 + yy, gx = cx0 - 1 + xx;
        float v = 0.f;
        if (gy >= 0 && gy < 224 && gx >= 0 && gx < 224)
            v = x[((b*3 + c)*224 + gy)*224 + gx];
        s_in[c][yy][xx] = v;
    }
    for (int i = tid; i < 1728; i += 256) {
        int oc = i / 27, tap = i % 27;
        s_w2[tap][oc] = w1[i];
    }
    if (tid < 64) s_b[tid] = b1[tid];
    __syncthreads();

    const int py = tid >> 4, px = tid & 15;
    const int ly = py * 2,  lx = px * 2;

    unsigned long long p2[3][4][4];
    #pragma unroll
    for (int c = 0; c < 3; c++)
        #pragma unroll
        for (int i = 0; i < 4; i++)
            #pragma unroll
            for (int j = 0; j < 4; j++) {
                float v = s_in[c][ly+i][lx+j];
                p2[c][i][j] = pack2(v, v);
            }

    float* outp = &g_h1[((b*64)*112 + (tpy0+py))*112 + (tpx0+px)];
    for (int oc = 0; oc < 64; oc += 2) {
        unsigned long long bb = pack2(s_b[oc], s_b[oc+1]);
        unsigned long long a00 = bb, a01 = bb, a10 = bb, a11 = bb;
        #pragma unroll
        for (int c = 0; c < 3; c++)
            #pragma unroll
            for (int ky = 0; ky < 3; ky++)
                #pragma unroll
                for (int kx = 0; kx < 3; kx++) {
                    int tap = c*9 + ky*3 + kx;
                    unsigned long long w = *(const unsigned long long*)&s_w2[tap][oc];
                    a00 = ffma2(p2[c][ky  ][kx  ], w, a00);
                    a01 = ffma2(p2[c][ky  ][kx+1], w, a01);
                    a10 = ffma2(p2[c][ky+1][kx  ], w, a10);
                    a11 = ffma2(p2[c][ky+1][kx+1], w, a11);
                }
        float v00a, v00b, v01a, v01b, v10a, v10b, v11a, v11b;
        unpack2(a00, v00a, v00b); unpack2(a01, v01a, v01b);
        unpack2(a10, v10a, v10b); unpack2(a11, v11a, v11b);
        float m0 = fmaxf(fmaxf(v00a, v01a), fmaxf(v10a, v11a));
        float m1 = fmaxf(fmaxf(v00b, v01b), fmaxf(v10b, v11b));
        outp[oc*112*112]     = leaky(m0);
        outp[(oc+1)*112*112] = leaky(m1);
    }
}

// ---------------------------------------------------------------------------
// Kernel 2: conv2 via mma.sync, per-tap cp.async double-buffered weights.
// smem 87 KB -> 2 CTAs/SM. Mainloop identical to R11-proven kernel.
// R14 FIX: weight chunk count 512 (64 oc x 8 x 16B), was 576 (OOB corruption).
// ---------------------------------------------------------------------------
#define C2_AHI     256
#define C2_ALO     26176                    // 256 + 180*144
#define C2_W0      52096                    // + 180*144
#define C2_WSTRIDE 18432                    // hi(9216) + lo(9216) per stage
#define C2_WLO_D   9216
#define C2_TOTAL   88960                    // 52096 + 2*18432
#define C2_ALO_D   25920

__device__ __forceinline__ void c2_issue_w(uint32_t sb, int tap, int stage, int tid)
{
    const char* ghi = (const char*)g_w2t_hi + tap*8192;   // 64 oc x 128 B packed
    const char* glo = (const char*)g_w2t_lo + tap*8192;
    uint32_t whi = sb + C2_W0 + (uint32_t)stage*C2_WSTRIDE;
    for (int i = tid; i < 512; i += 256) {                // i = oc*8 + j (16B chunks)
        int oc = i >> 3, j = i & 7;
        uint32_t d = whi + (uint32_t)oc*144u + (uint32_t)j*16u;
        cp_async16(d,            ghi + i*16);
        cp_async16(d + C2_WLO_D, glo + i*16);
    }
}

__global__ __launch_bounds__(256, 2) void conv2_kernel(const float* __restrict__ b2)
{
    extern __shared__ __align__(16) char smem[];
    const uint32_t sb = smem_to_u32(smem);
    const int tid  = threadIdx.x;
    const int lane = tid & 31;
    const int wid  = tid >> 5;

    const int t = blockIdx.x;               // 0..97 = 7 (y,16) x 14 (x,8)
    const int b = blockIdx.y;
    const int cy0 = (t / 14) * 16;
    const int cx0 = (t % 14) * 8;

    float* s_bias = (float*)smem;
    if (tid < 64) s_bias[tid] = b2[tid];

    // issue tap-0 weights immediately (overlaps with A staging)
    c2_issue_w(sb, 0, 0, tid);
    CP_COMMIT();

    // stage halo 18x10 x 64ic, split fp32 -> bf16 hi/lo on the fly
    {
        __nv_bfloat16* s_ahi = (__nv_bfloat16*)(smem + C2_AHI);
        __nv_bfloat16* s_alo = (__nv_bfloat16*)(smem + C2_ALO);
        for (int i = tid; i < 64*180; i += 256) {
            int ic  = i / 180;
            int pos = i % 180;
            int r = pos / 10, c = pos % 10;
            int gy = cy0 - 1 + r, gx = cx0 - 1 + c;
            float v = 0.f;
            if (gy >= 0 && gy < 112 && gx >= 0 && gx < 112)
                v = g_h1[(((unsigned)(b*64 + ic))*112u + gy)*112u + gx];
            __nv_bfloat16 hi = __float2bfloat16(v);
            __nv_bfloat16 lo = __float2bfloat16(v - __bfloat162float(hi));
            s_ahi[pos*72 + ic] = hi;
            s_alo[pos*72 + ic] = lo;
        }
    }
    CP_WAIT0();
    __syncthreads();

    uint32_t aBase;
    {
        int p = wid*16 + (lane & 15);
        int pos = (p >> 3)*10 + (p & 7);
        aBase = sb + C2_AHI + (uint32_t)pos*144u + (uint32_t)(lane >> 4)*16u;
    }
    uint32_t bOff[4];                       // per-lane offset within a W stage
    #pragma unroll
    for (int nb = 0; nb < 4; nb++) {
        int ocrow = nb*16 + (lane & 7) + ((lane >> 4) & 1)*8;
        bOff[nb] = (uint32_t)ocrow*144u + (uint32_t)((lane >> 3) & 1)*16u;
    }

    float acc[8][4];
    #pragma unroll
    for (int nf = 0; nf < 8; nf++)
        #pragma unroll
        for (int c = 0; c < 4; c++) acc[nf][c] = 0.f;

    for (int tap = 0; tap < 9; tap++) {
        const int stage = tap & 1;
        if (tap < 8) { c2_issue_w(sb, tap+1, stage ^ 1, tid); CP_COMMIT(); }

        const uint32_t wbase = sb + C2_W0 + (uint32_t)stage*C2_WSTRIDE;
        const uint32_t aS = (uint32_t)((tap/3)*10 + (tap%3)) * 144u;
        #pragma unroll
        for (int k = 0; k < 4; k++) {
            const uint32_t ko = (uint32_t)k * 32u;
            uint32_t ah[4], al[4];
            ldsm_x4(ah, aBase + aS + ko);
            ldsm_x4(al, aBase + C2_ALO_D + aS + ko);
            #pragma unroll
            for (int nb = 0; nb < 4; nb++) {
                uint32_t bh[4], bl[4];
                const uint32_t bbadr = wbase + bOff[nb] + ko;
                ldsm_x4(bh, bbadr);
                ldsm_x4(bl, bbadr + C2_WLO_D);
                mma_bf16(acc[2*nb],   ah, bh[0], bh[1]);   // hi*hi
                mma_bf16(acc[2*nb+1], ah, bh[2], bh[3]);
                mma_bf16(acc[2*nb],   ah, bl[0], bl[1]);   // hi*lo
                mma_bf16(acc[2*nb+1], ah, bl[2], bl[3]);
                mma_bf16(acc[2*nb],   al, bh[0], bh[1]);   // lo*hi
                mma_bf16(acc[2*nb+1], al, bh[2], bh[3]);
            }
        }
        if (tap < 8) CP_WAIT0();
        __syncthreads();    // next-stage writes visible; current-stage reads done
    }

    // D stage + scalar pool (proven; overlays A region)
    float* s_d = (float*)(smem + C2_AHI);
    #pragma unroll
    for (int nf = 0; nf < 8; nf++) {
        int oc = nf*8 + 2*(lane & 3);
        int p0 = wid*16 + (lane >> 2);
        s_d[p0*64 + oc]         = acc[nf][0];
        s_d[p0*64 + oc + 1]     = acc[nf][1];
        s_d[(p0+8)*64 + oc]     = acc[nf][2];
        s_d[(p0+8)*64 + oc + 1] = acc[nf][3];
    }
    __syncthreads();

    {
        int q   = tid >> 3;
        int oc0 = (tid & 7) * 8;
        int qy = q >> 2, qx = q & 3;
        int p00 = (qy*2)*8 + qx*2;
        int oy = (cy0 >> 1) + qy, ox = (cx0 >> 1) + qx;
        #pragma unroll
        for (int j = 0; j < 8; j++) {
            int oc = oc0 + j;
            float m = fmaxf(fmaxf(s_d[p00*64 + oc],     s_d[(p00+1)*64 + oc]),
                            fmaxf(s_d[(p00+8)*64 + oc], s_d[(p00+9)*64 + oc]));
            g_h2[(((unsigned)(b*64 + oc))*56u + oy)*56u + ox] = leaky(m + s_bias[oc]);
        }
    }
}

// ---------------------------------------------------------------------------
// Kernel 3: FC split-K partials, grid (196,4), warp = batch
// ---------------------------------------------------------------------------
__global__ __launch_bounds__(256) void fc_partial_kernel(const float* __restrict__ wfc)
{
    __shared__ __align__(16) float s_wt[10][1024];
    const int tid = threadIdx.x;
    const int k0  = blockIdx.x * 1024;

    for (int i = tid; i < 10240; i += 256) {
        int k = i / 10, c = i % 10;
        s_wt[c][k] = wfc[k0*10 + i];
    }
    __syncthreads();

    const int warp = tid >> 5, lane = tid & 31;
    const int b = blockIdx.y * 8 + warp;

    float acc[10];
    #pragma unroll
    for (int c = 0; c < 10; c++) acc[c] = 0.f;

    const float4* hb = (const float4*)&g_h2[b*200704 + k0];
    for (int k4 = lane; k4 < 256; k4 += 32) {
        float4 hv = hb[k4];
        #pragma unroll
        for (int c = 0; c < 10; c++) {
            float4 wv = *(const float4*)&s_wt[c][k4*4];
            acc[c] += hv.x*wv.x + hv.y*wv.y + hv.z*wv.z + hv.w*wv.w;
        }
    }
    #pragma unroll
    for (int c = 0; c < 10; c++) {
        #pragma unroll
        for (int off = 16; off; off >>= 1)
            acc[c] += __shfl_xor_sync(0xffffffffu, acc[c], off);
    }
    if (lane == 0) {
        #pragma unroll
        for (int c = 0; c < 10; c++)
            g_fcp[(blockIdx.x*32 + b)*10 + c] = acc[c];
    }
}

// ---------------------------------------------------------------------------
// Kernel 4: final deterministic reduction (proven)
// ---------------------------------------------------------------------------
__global__ __launch_bounds__(224) void fc_reduce_kernel(const float* __restrict__ bfc,
                                                        float* __restrict__ out)
{
    __shared__ float s_part[7][10];
    const int tid = threadIdx.x;
    const int b   = blockIdx.x;
    const int warp = tid >> 5, lane = tid & 31;

    float a[10];
    #pragma unroll
    for (int c = 0; c < 10; c++) a[c] = 0.f;

    if (tid < 196) {
        const float2* p = (const float2*)&g_fcp[(tid*32 + b)*10];
        #pragma unroll
        for (int h = 0; h < 5; h++) {
            float2 v = p[h];
            a[2*h]   = v.x;
            a[2*h+1] = v.y;
        }
    }
    #pragma unroll
    for (int c = 0; c < 10; c++) {
        #pragma unroll
        for (int off = 16; off; off >>= 1)
            a[c] += __shfl_xor_sync(0xffffffffu, a[c], off);
    }
    if (lane == 0)
        #pragma unroll
        for (int c = 0; c < 10; c++) s_part[warp][c] = a[c];
    __syncthreads();

    if (tid < 10) {
        float s = bfc[tid];
        #pragma unroll
        for (int w = 0; w < 7; w++) s += s_part[w][tid];
        out[b*10 + tid] = s;
    }
}

// ---------------------------------------------------------------------------
extern "C" void kernel_launch(void* const* d_in, const int* in_sizes, int n_in,
                              void* d_out, int out_size)
{
    const float* x   = (const float*)d_in[0];
    const float* w1  = (const float*)d_in[1];
    const float* b1  = (const float*)d_in[2];
    const float* w2  = (const float*)d_in[3];
    const float* b2  = (const float*)d_in[4];
    const float* wfc = (const float*)d_in[5];
    const float* bfc = (const float*)d_in[6];
    float* out = (float*)d_out;

    cudaFuncSetAttribute(conv2_kernel, cudaFuncAttributeMaxDynamicSharedMemorySize,
                         C2_TOTAL);

    prep_w2_kernel<<<36, 1024>>>(w2);
    conv1_kernel<<<dim3(49, 32), 256>>>(x, w1, b1);
    conv2_kernel<<<dim3(98, 32), 256, C2_TOTAL>>>(b2);
    fc_partial_kernel<<<dim3(196, 4), 256>>>(wfc);
    fc_reduce_kernel<<<32, 224>>>(bfc, out);
}